// round 8
// baseline (speedup 1.0000x reference)
#include <cuda_runtime.h>
#include <math.h>

#define Bsz 64
#define Nn  16384
#define Mm  128
#define Cc  1024
#define EPSF 1e-16f

#define GRP   8                          // batches per pipeline group
#define NGRP  (Bsz / GRP)                // 8 groups
#define RCH   32                         // read chunks per batch
#define RROWS (Nn / RCH)                 // 512 rows per chunk

// ---------------- scratch (device globals; no allocs allowed) ----------------
__device__ float g_s[Bsz * Nn];            // beta * sim        (4 MB)
__device__ float g_k[Bsz * Mm];            // key vectors
__device__ float g_prm[Bsz * 8];           // normk,beta,gate,gamma,s0,s1,s2
__device__ float g_part[Bsz * RCH * Mm];   // read partials     (1 MB)

// ---------------- helpers ----------------
__device__ __forceinline__ float softplusf(float x) {
    return fmaxf(x, 0.0f) + log1pf(expf(-fabsf(x)));
}
__device__ __forceinline__ float sigmoidf(float x) {
    return 1.0f / (1.0f + expf(-x));
}

__device__ __forceinline__ float blockReduceSum1024(float v) {
    __shared__ float sm[32];
    #pragma unroll
    for (int o = 16; o; o >>= 1) v += __shfl_xor_sync(0xffffffffu, v, o);
    int w = threadIdx.x >> 5, l = threadIdx.x & 31;
    if (l == 0) sm[w] = v;
    __syncthreads();
    if (w == 0) {
        v = sm[l];
        #pragma unroll
        for (int o = 16; o; o >>= 1) v += __shfl_xor_sync(0xffffffffu, v, o);
        if (l == 0) sm[0] = v;
    }
    __syncthreads();
    float r = sm[0];
    __syncthreads();
    return r;
}
__device__ __forceinline__ float blockReduceMax1024(float v) {
    __shared__ float sm[32];
    #pragma unroll
    for (int o = 16; o; o >>= 1) v = fmaxf(v, __shfl_xor_sync(0xffffffffu, v, o));
    int w = threadIdx.x >> 5, l = threadIdx.x & 31;
    if (l == 0) sm[w] = v;
    __syncthreads();
    if (w == 0) {
        v = sm[l];
        #pragma unroll
        for (int o = 16; o; o >>= 1) v = fmaxf(v, __shfl_xor_sync(0xffffffffu, v, o));
        if (l == 0) sm[0] = v;
    }
    __syncthreads();
    float r = sm[0];
    __syncthreads();
    return r;
}

// ---------------- kernel 1: projections ----------------
__global__ void __launch_bounds__(1024) proj_kernel(
    const float* __restrict__ ctrl,
    const float* __restrict__ key_w, const float* __restrict__ key_b,
    const float* __restrict__ beta_w, const float* __restrict__ beta_b,
    const float* __restrict__ gate_w, const float* __restrict__ gate_b,
    const float* __restrict__ shift_w, const float* __restrict__ shift_b,
    const float* __restrict__ gamma_w, const float* __restrict__ gamma_b)
{
    const int b = blockIdx.x, tid = threadIdx.x;
    const int lane = tid & 31, warp = tid >> 5;
    __shared__ float sc[Cc];
    __shared__ float pk[8][Mm];
    __shared__ float sd[32][6];

    sc[tid] = ctrl[b * Cc + tid];
    __syncthreads();

    const int col = tid & 127, chunk = tid >> 7;
    {
        float acc = 0.0f;
        const float* wp = key_w + (size_t)(chunk * 128) * Mm + col;
        const float* scp = sc + chunk * 128;
        #pragma unroll 8
        for (int i = 0; i < 128; i++) acc = fmaf(scp[i], wp[(size_t)i * Mm], acc);
        pk[chunk][col] = acc;
    }
    __syncthreads();

    float kf = 0.0f;
    if (tid < Mm) {
        float s = key_b[tid];
        #pragma unroll
        for (int j = 0; j < 8; j++) s += pk[j][tid];
        kf = tanhf(s);
        g_k[b * Mm + tid] = kf;
    }
    __syncthreads();
    if (tid < Mm) pk[0][tid] = kf * kf;
    __syncthreads();
    if (tid < 32) {
        float s = pk[0][tid] + pk[0][tid + 32] + pk[0][tid + 64] + pk[0][tid + 96];
        #pragma unroll
        for (int o = 16; o; o >>= 1) s += __shfl_xor_sync(0xffffffffu, s, o);
        if (tid == 0) g_prm[b * 8 + 0] = sqrtf(s);
    }

    {
        float v = sc[tid];
        float p[6];
        p[0] = v * beta_w[tid];
        p[1] = v * gate_w[tid];
        p[2] = v * gamma_w[tid];
        p[3] = v * shift_w[tid * 3 + 0];
        p[4] = v * shift_w[tid * 3 + 1];
        p[5] = v * shift_w[tid * 3 + 2];
        #pragma unroll
        for (int j = 0; j < 6; j++) {
            #pragma unroll
            for (int o = 16; o; o >>= 1) p[j] += __shfl_xor_sync(0xffffffffu, p[j], o);
        }
        if (lane == 0) {
            #pragma unroll
            for (int j = 0; j < 6; j++) sd[warp][j] = p[j];
        }
    }
    __syncthreads();
    if (tid < 32) {
        float q[6];
        #pragma unroll
        for (int j = 0; j < 6; j++) {
            q[j] = sd[tid][j];
            #pragma unroll
            for (int o = 16; o; o >>= 1) q[j] += __shfl_xor_sync(0xffffffffu, q[j], o);
        }
        if (tid == 0) {
            float beta  = softplusf(q[0] + beta_b[0]);
            float gate  = sigmoidf(q[1] + gate_b[0]);
            float gamma = 1.0f + softplusf(q[2] + gamma_b[0]);
            float l0 = q[3] + shift_b[0];
            float l1 = q[4] + shift_b[1];
            float l2 = q[5] + shift_b[2];
            float mx = fmaxf(l0, fmaxf(l1, l2));
            float e0 = expf(l0 - mx), e1 = expf(l1 - mx), e2 = expf(l2 - mx);
            float inv = 1.0f / (e0 + e1 + e2);
            g_prm[b * 8 + 1] = beta;
            g_prm[b * 8 + 2] = gate;
            g_prm[b * 8 + 3] = gamma;
            g_prm[b * 8 + 4] = e0 * inv;
            g_prm[b * 8 + 5] = e1 * inv;
            g_prm[b * 8 + 6] = e2 * inv;
        }
    }
}

// ---------------- kernel 2: content similarity for one group ----------------
// one warp per 4 rows; __ldg (NOT streaming) so the group's 64MB stays in L2
// for the read pass that follows in the pipeline.
__global__ void __launch_bounds__(256) sim_kernel(const float* __restrict__ mem,
                                                  int b0)
{
    const int task = (blockIdx.x * blockDim.x + threadIdx.x) >> 5;
    const int lane = threadIdx.x & 31;
    const int r0 = b0 * Nn + task * 4;
    const int b = r0 >> 14;

    float4 k4 = __ldg(((const float4*)g_k) + b * 32 + lane);
    const float4* mp = ((const float4*)mem) + (size_t)r0 * 32 + lane;
    float4 m0 = __ldg(mp);
    float4 m1 = __ldg(mp + 32);
    float4 m2 = __ldg(mp + 64);
    float4 m3 = __ldg(mp + 96);

    float d0 = m0.x * k4.x + m0.y * k4.y + m0.z * k4.z + m0.w * k4.w;
    float n0 = m0.x * m0.x + m0.y * m0.y + m0.z * m0.z + m0.w * m0.w;
    float d1 = m1.x * k4.x + m1.y * k4.y + m1.z * k4.z + m1.w * k4.w;
    float n1 = m1.x * m1.x + m1.y * m1.y + m1.z * m1.z + m1.w * m1.w;
    float d2 = m2.x * k4.x + m2.y * k4.y + m2.z * k4.z + m2.w * k4.w;
    float n2 = m2.x * m2.x + m2.y * m2.y + m2.z * m2.z + m2.w * m2.w;
    float d3 = m3.x * k4.x + m3.y * k4.y + m3.z * k4.z + m3.w * k4.w;
    float n3 = m3.x * m3.x + m3.y * m3.y + m3.z * m3.z + m3.w * m3.w;
    #pragma unroll
    for (int o = 16; o; o >>= 1) {
        d0 += __shfl_xor_sync(0xffffffffu, d0, o);
        n0 += __shfl_xor_sync(0xffffffffu, n0, o);
        d1 += __shfl_xor_sync(0xffffffffu, d1, o);
        n1 += __shfl_xor_sync(0xffffffffu, n1, o);
        d2 += __shfl_xor_sync(0xffffffffu, d2, o);
        n2 += __shfl_xor_sync(0xffffffffu, n2, o);
        d3 += __shfl_xor_sync(0xffffffffu, d3, o);
        n3 += __shfl_xor_sync(0xffffffffu, n3, o);
    }
    if (lane == 0) {
        float normk = g_prm[b * 8 + 0];
        float beta  = g_prm[b * 8 + 1];
        g_s[r0]     = beta * (d0 / (normk * sqrtf(n0) + EPSF));
        g_s[r0 + 1] = beta * (d1 / (normk * sqrtf(n1) + EPSF));
        g_s[r0 + 2] = beta * (d2 / (normk * sqrtf(n2) + EPSF));
        g_s[r0 + 3] = beta * (d3 / (normk * sqrtf(n3) + EPSF));
    }
}

// ---------------- kernel 3: softmax + gate + shift + sharpen (one group) ----------------
__global__ void __launch_bounds__(1024) weights_kernel(
    const float* __restrict__ prev, float* __restrict__ out, int b0)
{
    extern __shared__ float sw[];
    const int b = b0 + blockIdx.x, tid = threadIdx.x;
    const float gate  = g_prm[b * 8 + 2];
    const float gamma = g_prm[b * 8 + 3];
    const float s0 = g_prm[b * 8 + 4];
    const float s1 = g_prm[b * 8 + 5];
    const float s2 = g_prm[b * 8 + 6];

    const float4* s4 = (const float4*)(g_s + (size_t)b * Nn);
    const float4* p4 = (const float4*)(prev + (size_t)b * Nn);
    float4* sw4 = (float4*)sw;
    float4* o4 = (float4*)(out + (size_t)b * Nn);

    float4 sv[4];
    float mx = -3.4e38f;
    #pragma unroll
    for (int i = 0; i < 4; i++) {
        sv[i] = __ldg(s4 + i * 1024 + tid);
        mx = fmaxf(mx, fmaxf(fmaxf(sv[i].x, sv[i].y), fmaxf(sv[i].z, sv[i].w)));
    }
    mx = blockReduceMax1024(mx);

    float lsum = 0.0f;
    #pragma unroll
    for (int i = 0; i < 4; i++) {
        sv[i].x = __expf(sv[i].x - mx);
        sv[i].y = __expf(sv[i].y - mx);
        sv[i].z = __expf(sv[i].z - mx);
        sv[i].w = __expf(sv[i].w - mx);
        lsum += sv[i].x + sv[i].y + sv[i].z + sv[i].w;
    }
    float Z = blockReduceSum1024(lsum);

    const float gz = gate / Z;
    const float og = 1.0f - gate;
    #pragma unroll
    for (int i = 0; i < 4; i++) {
        float4 pv = __ldg(p4 + i * 1024 + tid);
        float4 wv;
        wv.x = sv[i].x * gz + og * pv.x;
        wv.y = sv[i].y * gz + og * pv.y;
        wv.z = sv[i].z * gz + og * pv.z;
        wv.w = sv[i].w * gz + og * pv.w;
        sw4[i * 1024 + tid] = wv;
        sv[i] = wv;
    }
    __syncthreads();

    float4 wp[4];
    float psum = 0.0f;
    #pragma unroll
    for (int i = 0; i < 4; i++) {
        int n = (i * 1024 + tid) * 4;
        float wl = sw[(n - 1) & (Nn - 1)];
        float wr = sw[(n + 4) & (Nn - 1)];
        float4 wc = sv[i];
        float4 w2;
        w2.x = s0 * wl   + s1 * wc.x + s2 * wc.y;
        w2.y = s0 * wc.x + s1 * wc.y + s2 * wc.z;
        w2.z = s0 * wc.y + s1 * wc.z + s2 * wc.w;
        w2.w = s0 * wc.z + s1 * wc.w + s2 * wr;
        wp[i].x = exp2f(gamma * __log2f(w2.x));
        wp[i].y = exp2f(gamma * __log2f(w2.y));
        wp[i].z = exp2f(gamma * __log2f(w2.z));
        wp[i].w = exp2f(gamma * __log2f(w2.w));
        psum += wp[i].x + wp[i].y + wp[i].z + wp[i].w;
    }
    float S = blockReduceSum1024(psum);
    float inv = 1.0f / (S + EPSF);
    #pragma unroll
    for (int i = 0; i < 4; i++) {
        float4 ov;
        ov.x = wp[i].x * inv;
        ov.y = wp[i].y * inv;
        ov.z = wp[i].z * inv;
        ov.w = wp[i].w * inv;
        o4[i * 1024 + tid] = ov;
    }
}

// ---------------- kernel 4: weighted read partials (one group) ----------------
// Should hit L2: sim(g) just loaded this group's memory. __ldcs: dead after.
__global__ void __launch_bounds__(256, 8) read_kernel(
    const float* __restrict__ mem, const float* __restrict__ wts, int b0)
{
    const int b = b0 + (blockIdx.x >> 5);     // /RCH
    const int c = blockIdx.x & (RCH - 1);
    const int wid = threadIdx.x >> 5, lane = threadIdx.x & 31;
    const int n0 = c * RROWS;

    float4 acc = make_float4(0.f, 0.f, 0.f, 0.f);
    for (int r = n0 + wid; r < n0 + RROWS; r += 8) {
        size_t row = (size_t)b * Nn + r;
        float wv = __ldg(wts + row);
        float4 m4 = __ldcs(((const float4*)mem) + row * 32 + lane);
        acc.x = fmaf(wv, m4.x, acc.x);
        acc.y = fmaf(wv, m4.y, acc.y);
        acc.z = fmaf(wv, m4.z, acc.z);
        acc.w = fmaf(wv, m4.w, acc.w);
    }

    __shared__ float sm[8][Mm];
    sm[wid][lane * 4 + 0] = acc.x;
    sm[wid][lane * 4 + 1] = acc.y;
    sm[wid][lane * 4 + 2] = acc.z;
    sm[wid][lane * 4 + 3] = acc.w;
    __syncthreads();
    if (threadIdx.x < Mm) {
        float s = 0.0f;
        #pragma unroll
        for (int j = 0; j < 8; j++) s += sm[j][threadIdx.x];
        g_part[((size_t)b * RCH + c) * Mm + threadIdx.x] = s;
    }
}

// ---------------- kernel 5: fold partials ----------------
__global__ void __launch_bounds__(256) reduce_kernel(float* __restrict__ out)
{
    int idx = blockIdx.x * blockDim.x + threadIdx.x;
    if (idx >= Bsz * Mm) return;
    int b = idx >> 7, m = idx & 127;
    float s = 0.0f;
    #pragma unroll
    for (int j = 0; j < RCH; j++) s += g_part[((size_t)b * RCH + j) * Mm + m];
    out[(size_t)Bsz * Nn + idx] = s;
}

// ---------------- launch: 3-stream software pipeline over batch groups ----------------
extern "C" void kernel_launch(void* const* d_in, const int* in_sizes, int n_in,
                              void* d_out, int out_size)
{
    const float* ctrl    = (const float*)d_in[0];
    const float* prev    = (const float*)d_in[1];
    const float* mem     = (const float*)d_in[2];
    const float* key_w   = (const float*)d_in[3];
    const float* key_b   = (const float*)d_in[4];
    const float* beta_w  = (const float*)d_in[5];
    const float* beta_b  = (const float*)d_in[6];
    const float* gate_w  = (const float*)d_in[7];
    const float* gate_b  = (const float*)d_in[8];
    const float* shift_w = (const float*)d_in[9];
    const float* shift_b = (const float*)d_in[10];
    const float* gamma_w = (const float*)d_in[11];
    const float* gamma_b = (const float*)d_in[12];
    float* out = (float*)d_out;

    static bool init_done = false;
    static cudaStream_t sA, sB, sC;
    static cudaEvent_t evFork, evSim[NGRP], evW[NGRP], evJoinA, evJoinB, evJoinC;
    if (!init_done) {
        cudaFuncSetAttribute(weights_kernel,
                             cudaFuncAttributeMaxDynamicSharedMemorySize,
                             Nn * (int)sizeof(float));
        int lo, hi;
        cudaDeviceGetStreamPriorityRange(&lo, &hi);
        cudaStreamCreateWithPriority(&sA, cudaStreamNonBlocking, lo);  // sim: low prio
        cudaStreamCreateWithPriority(&sB, cudaStreamNonBlocking, hi);  // weights: high
        cudaStreamCreateWithPriority(&sC, cudaStreamNonBlocking, hi);  // read: high
        cudaEventCreateWithFlags(&evFork, cudaEventDisableTiming);
        for (int g = 0; g < NGRP; g++) {
            cudaEventCreateWithFlags(&evSim[g], cudaEventDisableTiming);
            cudaEventCreateWithFlags(&evW[g], cudaEventDisableTiming);
        }
        cudaEventCreateWithFlags(&evJoinA, cudaEventDisableTiming);
        cudaEventCreateWithFlags(&evJoinB, cudaEventDisableTiming);
        cudaEventCreateWithFlags(&evJoinC, cudaEventDisableTiming);
        init_done = true;
    }

    // proj on the capture (default) stream
    proj_kernel<<<Bsz, 1024>>>(ctrl, key_w, key_b, beta_w, beta_b,
                               gate_w, gate_b, shift_w, shift_b, gamma_w, gamma_b);
    cudaEventRecord(evFork, 0);
    cudaStreamWaitEvent(sA, evFork, 0);

    for (int g = 0; g < NGRP; g++) {
        int b0 = g * GRP;
        sim_kernel<<<GRP * Nn / 32, 256, 0, sA>>>(mem, b0);
        cudaEventRecord(evSim[g], sA);

        cudaStreamWaitEvent(sB, evSim[g], 0);
        weights_kernel<<<GRP, 1024, Nn * sizeof(float), sB>>>(prev, out, b0);
        cudaEventRecord(evW[g], sB);

        cudaStreamWaitEvent(sC, evW[g], 0);
        read_kernel<<<GRP * RCH, 256, 0, sC>>>(mem, out, b0);
    }

    // join all forked streams back into the capture stream
    cudaEventRecord(evJoinA, sA);
    cudaEventRecord(evJoinB, sB);
    cudaEventRecord(evJoinC, sC);
    cudaStreamWaitEvent(0, evJoinA, 0);
    cudaStreamWaitEvent(0, evJoinB, 0);
    cudaStreamWaitEvent(0, evJoinC, 0);

    reduce_kernel<<<(Bsz * Mm + 255) / 256, 256>>>(out);
}

// round 9
// speedup vs baseline: 1.2262x; 1.2262x over previous
#include <cuda_runtime.h>
#include <math.h>

#define Bsz 64
#define Nn  16384
#define Mm  128
#define Cc  1024
#define EPSF 1e-16f

#define HB    (Bsz / 2)                  // batches per half (32)
#define RCH   16                         // read chunks per batch
#define RROWS (Nn / RCH)                 // 1024 rows per chunk

// ---------------- scratch (device globals; no allocs allowed) ----------------
__device__ float g_s[Bsz * Nn];            // beta * sim        (4 MB)
__device__ float g_k[Bsz * Mm];            // key vectors
__device__ float g_prm[Bsz * 8];           // normk,beta,gate,gamma,s0,s1,s2
__device__ float g_part[Bsz * RCH * Mm];   // read partials

// ---------------- helpers ----------------
__device__ __forceinline__ float softplusf(float x) {
    return fmaxf(x, 0.0f) + log1pf(expf(-fabsf(x)));
}
__device__ __forceinline__ float sigmoidf(float x) {
    return 1.0f / (1.0f + expf(-x));
}

__device__ __forceinline__ float blockReduceSum1024(float v) {
    __shared__ float sm[32];
    #pragma unroll
    for (int o = 16; o; o >>= 1) v += __shfl_xor_sync(0xffffffffu, v, o);
    int w = threadIdx.x >> 5, l = threadIdx.x & 31;
    if (l == 0) sm[w] = v;
    __syncthreads();
    if (w == 0) {
        v = sm[l];
        #pragma unroll
        for (int o = 16; o; o >>= 1) v += __shfl_xor_sync(0xffffffffu, v, o);
        if (l == 0) sm[0] = v;
    }
    __syncthreads();
    float r = sm[0];
    __syncthreads();
    return r;
}
__device__ __forceinline__ float blockReduceMax1024(float v) {
    __shared__ float sm[32];
    #pragma unroll
    for (int o = 16; o; o >>= 1) v = fmaxf(v, __shfl_xor_sync(0xffffffffu, v, o));
    int w = threadIdx.x >> 5, l = threadIdx.x & 31;
    if (l == 0) sm[w] = v;
    __syncthreads();
    if (w == 0) {
        v = sm[l];
        #pragma unroll
        for (int o = 16; o; o >>= 1) v = fmaxf(v, __shfl_xor_sync(0xffffffffu, v, o));
        if (l == 0) sm[0] = v;
    }
    __syncthreads();
    float r = sm[0];
    __syncthreads();
    return r;
}

// ---------------- kernel 1: projections (all batches) ----------------
__global__ void __launch_bounds__(1024) proj_kernel(
    const float* __restrict__ ctrl,
    const float* __restrict__ key_w, const float* __restrict__ key_b,
    const float* __restrict__ beta_w, const float* __restrict__ beta_b,
    const float* __restrict__ gate_w, const float* __restrict__ gate_b,
    const float* __restrict__ shift_w, const float* __restrict__ shift_b,
    const float* __restrict__ gamma_w, const float* __restrict__ gamma_b)
{
    const int b = blockIdx.x, tid = threadIdx.x;
    const int lane = tid & 31, warp = tid >> 5;
    __shared__ float sc[Cc];
    __shared__ float pk[8][Mm];
    __shared__ float sd[32][6];

    sc[tid] = ctrl[b * Cc + tid];
    __syncthreads();

    const int col = tid & 127, chunk = tid >> 7;
    {
        float acc = 0.0f;
        const float* wp = key_w + (size_t)(chunk * 128) * Mm + col;
        const float* scp = sc + chunk * 128;
        #pragma unroll 8
        for (int i = 0; i < 128; i++) acc = fmaf(scp[i], wp[(size_t)i * Mm], acc);
        pk[chunk][col] = acc;
    }
    __syncthreads();

    float kf = 0.0f;
    if (tid < Mm) {
        float s = key_b[tid];
        #pragma unroll
        for (int j = 0; j < 8; j++) s += pk[j][tid];
        kf = tanhf(s);
        g_k[b * Mm + tid] = kf;
    }
    __syncthreads();
    if (tid < Mm) pk[0][tid] = kf * kf;
    __syncthreads();
    if (tid < 32) {
        float s = pk[0][tid] + pk[0][tid + 32] + pk[0][tid + 64] + pk[0][tid + 96];
        #pragma unroll
        for (int o = 16; o; o >>= 1) s += __shfl_xor_sync(0xffffffffu, s, o);
        if (tid == 0) g_prm[b * 8 + 0] = sqrtf(s);
    }

    {
        float v = sc[tid];
        float p[6];
        p[0] = v * beta_w[tid];
        p[1] = v * gate_w[tid];
        p[2] = v * gamma_w[tid];
        p[3] = v * shift_w[tid * 3 + 0];
        p[4] = v * shift_w[tid * 3 + 1];
        p[5] = v * shift_w[tid * 3 + 2];
        #pragma unroll
        for (int j = 0; j < 6; j++) {
            #pragma unroll
            for (int o = 16; o; o >>= 1) p[j] += __shfl_xor_sync(0xffffffffu, p[j], o);
        }
        if (lane == 0) {
            #pragma unroll
            for (int j = 0; j < 6; j++) sd[warp][j] = p[j];
        }
    }
    __syncthreads();
    if (tid < 32) {
        float q[6];
        #pragma unroll
        for (int j = 0; j < 6; j++) {
            q[j] = sd[tid][j];
            #pragma unroll
            for (int o = 16; o; o >>= 1) q[j] += __shfl_xor_sync(0xffffffffu, q[j], o);
        }
        if (tid == 0) {
            float beta  = softplusf(q[0] + beta_b[0]);
            float gate  = sigmoidf(q[1] + gate_b[0]);
            float gamma = 1.0f + softplusf(q[2] + gamma_b[0]);
            float l0 = q[3] + shift_b[0];
            float l1 = q[4] + shift_b[1];
            float l2 = q[5] + shift_b[2];
            float mx = fmaxf(l0, fmaxf(l1, l2));
            float e0 = expf(l0 - mx), e1 = expf(l1 - mx), e2 = expf(l2 - mx);
            float inv = 1.0f / (e0 + e1 + e2);
            g_prm[b * 8 + 1] = beta;
            g_prm[b * 8 + 2] = gate;
            g_prm[b * 8 + 3] = gamma;
            g_prm[b * 8 + 4] = e0 * inv;
            g_prm[b * 8 + 5] = e1 * inv;
            g_prm[b * 8 + 6] = e2 * inv;
        }
    }
}

// ---------------- kernel 2: content similarity for a half ----------------
// one warp per 4 rows; streaming loads (no reuse across passes: 512MB >> L2)
__global__ void __launch_bounds__(256) sim_kernel(const float* __restrict__ mem,
                                                  int b0)
{
    const int task = (blockIdx.x * blockDim.x + threadIdx.x) >> 5;
    const int lane = threadIdx.x & 31;
    const int r0 = b0 * Nn + task * 4;
    const int b = r0 >> 14;

    float4 k4 = __ldg(((const float4*)g_k) + b * 32 + lane);
    const float4* mp = ((const float4*)mem) + (size_t)r0 * 32 + lane;
    float4 m0 = __ldcs(mp);
    float4 m1 = __ldcs(mp + 32);
    float4 m2 = __ldcs(mp + 64);
    float4 m3 = __ldcs(mp + 96);

    float d0 = m0.x * k4.x + m0.y * k4.y + m0.z * k4.z + m0.w * k4.w;
    float n0 = m0.x * m0.x + m0.y * m0.y + m0.z * m0.z + m0.w * m0.w;
    float d1 = m1.x * k4.x + m1.y * k4.y + m1.z * k4.z + m1.w * k4.w;
    float n1 = m1.x * m1.x + m1.y * m1.y + m1.z * m1.z + m1.w * m1.w;
    float d2 = m2.x * k4.x + m2.y * k4.y + m2.z * k4.z + m2.w * k4.w;
    float n2 = m2.x * m2.x + m2.y * m2.y + m2.z * m2.z + m2.w * m2.w;
    float d3 = m3.x * k4.x + m3.y * k4.y + m3.z * k4.z + m3.w * k4.w;
    float n3 = m3.x * m3.x + m3.y * m3.y + m3.z * m3.z + m3.w * m3.w;
    #pragma unroll
    for (int o = 16; o; o >>= 1) {
        d0 += __shfl_xor_sync(0xffffffffu, d0, o);
        n0 += __shfl_xor_sync(0xffffffffu, n0, o);
        d1 += __shfl_xor_sync(0xffffffffu, d1, o);
        n1 += __shfl_xor_sync(0xffffffffu, n1, o);
        d2 += __shfl_xor_sync(0xffffffffu, d2, o);
        n2 += __shfl_xor_sync(0xffffffffu, n2, o);
        d3 += __shfl_xor_sync(0xffffffffu, d3, o);
        n3 += __shfl_xor_sync(0xffffffffu, n3, o);
    }
    if (lane == 0) {
        float normk = g_prm[b * 8 + 0];
        float beta  = g_prm[b * 8 + 1];
        g_s[r0]     = beta * (d0 / (normk * sqrtf(n0) + EPSF));
        g_s[r0 + 1] = beta * (d1 / (normk * sqrtf(n1) + EPSF));
        g_s[r0 + 2] = beta * (d2 / (normk * sqrtf(n2) + EPSF));
        g_s[r0 + 3] = beta * (d3 / (normk * sqrtf(n3) + EPSF));
    }
}

// ---------------- kernel 3: softmax + gate + shift + sharpen (a half) ----------------
__global__ void __launch_bounds__(1024) weights_kernel(
    const float* __restrict__ prev, float* __restrict__ out, int b0)
{
    extern __shared__ float sw[];
    const int b = b0 + blockIdx.x, tid = threadIdx.x;
    const float gate  = g_prm[b * 8 + 2];
    const float gamma = g_prm[b * 8 + 3];
    const float s0 = g_prm[b * 8 + 4];
    const float s1 = g_prm[b * 8 + 5];
    const float s2 = g_prm[b * 8 + 6];

    const float4* s4 = (const float4*)(g_s + (size_t)b * Nn);
    const float4* p4 = (const float4*)(prev + (size_t)b * Nn);
    float4* sw4 = (float4*)sw;
    float4* o4 = (float4*)(out + (size_t)b * Nn);

    float4 sv[4];
    float mx = -3.4e38f;
    #pragma unroll
    for (int i = 0; i < 4; i++) {
        sv[i] = __ldg(s4 + i * 1024 + tid);
        mx = fmaxf(mx, fmaxf(fmaxf(sv[i].x, sv[i].y), fmaxf(sv[i].z, sv[i].w)));
    }
    mx = blockReduceMax1024(mx);

    float lsum = 0.0f;
    #pragma unroll
    for (int i = 0; i < 4; i++) {
        sv[i].x = __expf(sv[i].x - mx);
        sv[i].y = __expf(sv[i].y - mx);
        sv[i].z = __expf(sv[i].z - mx);
        sv[i].w = __expf(sv[i].w - mx);
        lsum += sv[i].x + sv[i].y + sv[i].z + sv[i].w;
    }
    float Z = blockReduceSum1024(lsum);

    const float gz = gate / Z;
    const float og = 1.0f - gate;
    #pragma unroll
    for (int i = 0; i < 4; i++) {
        float4 pv = __ldg(p4 + i * 1024 + tid);
        float4 wv;
        wv.x = sv[i].x * gz + og * pv.x;
        wv.y = sv[i].y * gz + og * pv.y;
        wv.z = sv[i].z * gz + og * pv.z;
        wv.w = sv[i].w * gz + og * pv.w;
        sw4[i * 1024 + tid] = wv;
        sv[i] = wv;
    }
    __syncthreads();

    float4 wp[4];
    float psum = 0.0f;
    #pragma unroll
    for (int i = 0; i < 4; i++) {
        int n = (i * 1024 + tid) * 4;
        float wl = sw[(n - 1) & (Nn - 1)];
        float wr = sw[(n + 4) & (Nn - 1)];
        float4 wc = sv[i];
        float4 w2;
        w2.x = s0 * wl   + s1 * wc.x + s2 * wc.y;
        w2.y = s0 * wc.x + s1 * wc.y + s2 * wc.z;
        w2.z = s0 * wc.y + s1 * wc.z + s2 * wc.w;
        w2.w = s0 * wc.z + s1 * wc.w + s2 * wr;
        wp[i].x = exp2f(gamma * __log2f(w2.x));   // strictly positive
        wp[i].y = exp2f(gamma * __log2f(w2.y));
        wp[i].z = exp2f(gamma * __log2f(w2.z));
        wp[i].w = exp2f(gamma * __log2f(w2.w));
        psum += wp[i].x + wp[i].y + wp[i].z + wp[i].w;
    }
    float S = blockReduceSum1024(psum);
    float inv = 1.0f / (S + EPSF);
    #pragma unroll
    for (int i = 0; i < 4; i++) {
        float4 ov;
        ov.x = wp[i].x * inv;
        ov.y = wp[i].y * inv;
        ov.z = wp[i].z * inv;
        ov.w = wp[i].w * inv;
        o4[i * 1024 + tid] = ov;
    }
}

// ---------------- kernel 4: weighted read partials (a half) ----------------
__global__ void __launch_bounds__(256, 8) read_kernel(
    const float* __restrict__ mem, const float* __restrict__ wts, int b0)
{
    const int b = b0 + (blockIdx.x >> 4);     // /RCH
    const int c = blockIdx.x & (RCH - 1);
    const int wid = threadIdx.x >> 5, lane = threadIdx.x & 31;
    const int n0 = c * RROWS;

    float4 acc = make_float4(0.f, 0.f, 0.f, 0.f);
    for (int r = n0 + wid; r < n0 + RROWS; r += 8) {
        size_t row = (size_t)b * Nn + r;
        float wv = __ldg(wts + row);
        float4 m4 = __ldcs(((const float4*)mem) + row * 32 + lane);
        acc.x = fmaf(wv, m4.x, acc.x);
        acc.y = fmaf(wv, m4.y, acc.y);
        acc.z = fmaf(wv, m4.z, acc.z);
        acc.w = fmaf(wv, m4.w, acc.w);
    }

    __shared__ float sm[8][Mm];
    sm[wid][lane * 4 + 0] = acc.x;
    sm[wid][lane * 4 + 1] = acc.y;
    sm[wid][lane * 4 + 2] = acc.z;
    sm[wid][lane * 4 + 3] = acc.w;
    __syncthreads();
    if (threadIdx.x < Mm) {
        float s = 0.0f;
        #pragma unroll
        for (int j = 0; j < 8; j++) s += sm[j][threadIdx.x];
        g_part[((size_t)b * RCH + c) * Mm + threadIdx.x] = s;
    }
}

// ---------------- kernel 5: fold partials (all batches) ----------------
__global__ void __launch_bounds__(256) reduce_kernel(float* __restrict__ out)
{
    int idx = blockIdx.x * blockDim.x + threadIdx.x;
    if (idx >= Bsz * Mm) return;
    int b = idx >> 7, m = idx & 127;
    float s = 0.0f;
    #pragma unroll
    for (int j = 0; j < RCH; j++) s += g_part[((size_t)b * RCH + j) * Mm + m];
    out[(size_t)Bsz * Nn + idx] = s;
}

// ---------------- launch: two concurrent half-chains (bubble filling) ----------------
extern "C" void kernel_launch(void* const* d_in, const int* in_sizes, int n_in,
                              void* d_out, int out_size)
{
    const float* ctrl    = (const float*)d_in[0];
    const float* prev    = (const float*)d_in[1];
    const float* mem     = (const float*)d_in[2];
    const float* key_w   = (const float*)d_in[3];
    const float* key_b   = (const float*)d_in[4];
    const float* beta_w  = (const float*)d_in[5];
    const float* beta_b  = (const float*)d_in[6];
    const float* gate_w  = (const float*)d_in[7];
    const float* gate_b  = (const float*)d_in[8];
    const float* shift_w = (const float*)d_in[9];
    const float* shift_b = (const float*)d_in[10];
    const float* gamma_w = (const float*)d_in[11];
    const float* gamma_b = (const float*)d_in[12];
    float* out = (float*)d_out;

    static bool init_done = false;
    static cudaStream_t s0, s1;
    static cudaEvent_t evFork, evJoin0, evJoin1;
    if (!init_done) {
        cudaFuncSetAttribute(weights_kernel,
                             cudaFuncAttributeMaxDynamicSharedMemorySize,
                             Nn * (int)sizeof(float));
        cudaStreamCreateWithFlags(&s0, cudaStreamNonBlocking);
        cudaStreamCreateWithFlags(&s1, cudaStreamNonBlocking);
        cudaEventCreateWithFlags(&evFork, cudaEventDisableTiming);
        cudaEventCreateWithFlags(&evJoin0, cudaEventDisableTiming);
        cudaEventCreateWithFlags(&evJoin1, cudaEventDisableTiming);
        init_done = true;
    }

    proj_kernel<<<Bsz, 1024>>>(ctrl, key_w, key_b, beta_w, beta_b,
                               gate_w, gate_b, shift_w, shift_b, gamma_w, gamma_b);
    cudaEventRecord(evFork, 0);
    cudaStreamWaitEvent(s0, evFork, 0);
    cudaStreamWaitEvent(s1, evFork, 0);

    // half chains: each serial within its stream, concurrent across streams
    sim_kernel<<<HB * Nn / 32, 256, 0, s0>>>(mem, 0);
    weights_kernel<<<HB, 1024, Nn * sizeof(float), s0>>>(prev, out, 0);
    read_kernel<<<HB * RCH, 256, 0, s0>>>(mem, out, 0);

    sim_kernel<<<HB * Nn / 32, 256, 0, s1>>>(mem, HB);
    weights_kernel<<<HB, 1024, Nn * sizeof(float), s1>>>(prev, out, HB);
    read_kernel<<<HB * RCH, 256, 0, s1>>>(mem, out, HB);

    cudaEventRecord(evJoin0, s0);
    cudaEventRecord(evJoin1, s1);
    cudaStreamWaitEvent(0, evJoin0, 0);
    cudaStreamWaitEvent(0, evJoin1, 0);

    reduce_kernel<<<(Bsz * Mm + 255) / 256, 256>>>(out);
}

// round 10
// speedup vs baseline: 1.5154x; 1.2359x over previous
#include <cuda_runtime.h>
#include <math.h>

#define Bsz 64
#define Nn  16384
#define Mm  128
#define Cc  1024
#define EPSF 1e-16f

#define RCHUNKS 16                       // read chunks per batch
#define RROWS   (Nn / RCHUNKS)           // 1024 rows per chunk

// ---------------- scratch (device globals; no allocs allowed) ----------------
__device__ float g_s[Bsz * Nn];              // beta * sim        (4 MB)
__device__ float g_k[Bsz * Mm];              // key vectors
__device__ float g_prm[Bsz * 8];             // normk,beta,gate,gamma,s0,s1,s2
__device__ float g_part[Bsz * RCHUNKS * Mm]; // read partials     (512 KB)

// ---------------- helpers ----------------
__device__ __forceinline__ float softplusf(float x) {
    return fmaxf(x, 0.0f) + log1pf(expf(-fabsf(x)));
}
__device__ __forceinline__ float sigmoidf(float x) {
    return 1.0f / (1.0f + expf(-x));
}

__device__ __forceinline__ float blockReduceSum1024(float v) {
    __shared__ float sm[32];
    #pragma unroll
    for (int o = 16; o; o >>= 1) v += __shfl_xor_sync(0xffffffffu, v, o);
    int w = threadIdx.x >> 5, l = threadIdx.x & 31;
    if (l == 0) sm[w] = v;
    __syncthreads();
    if (w == 0) {
        v = sm[l];
        #pragma unroll
        for (int o = 16; o; o >>= 1) v += __shfl_xor_sync(0xffffffffu, v, o);
        if (l == 0) sm[0] = v;
    }
    __syncthreads();
    float r = sm[0];
    __syncthreads();
    return r;
}
__device__ __forceinline__ float blockReduceMax1024(float v) {
    __shared__ float sm[32];
    #pragma unroll
    for (int o = 16; o; o >>= 1) v = fmaxf(v, __shfl_xor_sync(0xffffffffu, v, o));
    int w = threadIdx.x >> 5, l = threadIdx.x & 31;
    if (l == 0) sm[w] = v;
    __syncthreads();
    if (w == 0) {
        v = sm[l];
        #pragma unroll
        for (int o = 16; o; o >>= 1) v = fmaxf(v, __shfl_xor_sync(0xffffffffu, v, o));
        if (l == 0) sm[0] = v;
    }
    __syncthreads();
    float r = sm[0];
    __syncthreads();
    return r;
}

// ---------------- kernel 1: projections ----------------
__global__ void __launch_bounds__(1024) proj_kernel(
    const float* __restrict__ ctrl,
    const float* __restrict__ key_w, const float* __restrict__ key_b,
    const float* __restrict__ beta_w, const float* __restrict__ beta_b,
    const float* __restrict__ gate_w, const float* __restrict__ gate_b,
    const float* __restrict__ shift_w, const float* __restrict__ shift_b,
    const float* __restrict__ gamma_w, const float* __restrict__ gamma_b)
{
    const int b = blockIdx.x, tid = threadIdx.x;
    const int lane = tid & 31, warp = tid >> 5;
    __shared__ float sc[Cc];
    __shared__ float pk[8][Mm];
    __shared__ float sd[32][6];

    sc[tid] = ctrl[b * Cc + tid];
    __syncthreads();

    const int col = tid & 127, chunk = tid >> 7;
    {
        float acc = 0.0f;
        const float* wp = key_w + (size_t)(chunk * 128) * Mm + col;
        const float* scp = sc + chunk * 128;
        #pragma unroll 8
        for (int i = 0; i < 128; i++) acc = fmaf(scp[i], wp[(size_t)i * Mm], acc);
        pk[chunk][col] = acc;
    }
    __syncthreads();

    float kf = 0.0f;
    if (tid < Mm) {
        float s = key_b[tid];
        #pragma unroll
        for (int j = 0; j < 8; j++) s += pk[j][tid];
        kf = tanhf(s);
        g_k[b * Mm + tid] = kf;
    }
    __syncthreads();
    if (tid < Mm) pk[0][tid] = kf * kf;
    __syncthreads();
    if (tid < 32) {
        float s = pk[0][tid] + pk[0][tid + 32] + pk[0][tid + 64] + pk[0][tid + 96];
        #pragma unroll
        for (int o = 16; o; o >>= 1) s += __shfl_xor_sync(0xffffffffu, s, o);
        if (tid == 0) g_prm[b * 8 + 0] = sqrtf(s);
    }

    {
        float v = sc[tid];
        float p[6];
        p[0] = v * beta_w[tid];
        p[1] = v * gate_w[tid];
        p[2] = v * gamma_w[tid];
        p[3] = v * shift_w[tid * 3 + 0];
        p[4] = v * shift_w[tid * 3 + 1];
        p[5] = v * shift_w[tid * 3 + 2];
        #pragma unroll
        for (int j = 0; j < 6; j++) {
            #pragma unroll
            for (int o = 16; o; o >>= 1) p[j] += __shfl_xor_sync(0xffffffffu, p[j], o);
        }
        if (lane == 0) {
            #pragma unroll
            for (int j = 0; j < 6; j++) sd[warp][j] = p[j];
        }
    }
    __syncthreads();
    if (tid < 32) {
        float q[6];
        #pragma unroll
        for (int j = 0; j < 6; j++) {
            q[j] = sd[tid][j];
            #pragma unroll
            for (int o = 16; o; o >>= 1) q[j] += __shfl_xor_sync(0xffffffffu, q[j], o);
        }
        if (tid == 0) {
            float beta  = softplusf(q[0] + beta_b[0]);
            float gate  = sigmoidf(q[1] + gate_b[0]);
            float gamma = 1.0f + softplusf(q[2] + gamma_b[0]);
            float l0 = q[3] + shift_b[0];
            float l1 = q[4] + shift_b[1];
            float l2 = q[5] + shift_b[2];
            float mx = fmaxf(l0, fmaxf(l1, l2));
            float e0 = expf(l0 - mx), e1 = expf(l1 - mx), e2 = expf(l2 - mx);
            float inv = 1.0f / (e0 + e1 + e2);
            g_prm[b * 8 + 1] = beta;
            g_prm[b * 8 + 2] = gate;
            g_prm[b * 8 + 3] = gamma;
            g_prm[b * 8 + 4] = e0 * inv;
            g_prm[b * 8 + 5] = e1 * inv;
            g_prm[b * 8 + 6] = e2 * inv;
        }
    }
}

// ---------------- kernel 2: content similarity (memory pass 1) ----------------
// one warp per 4 memory rows; 4 independent streaming float4 loads per lane
__global__ void __launch_bounds__(256) sim_kernel(const float* __restrict__ mem)
{
    const int task = (blockIdx.x * blockDim.x + threadIdx.x) >> 5;
    const int lane = threadIdx.x & 31;
    const int r0 = task * 4;                // four consecutive rows, same batch
    const int b = r0 >> 14;

    float4 k4 = __ldg(((const float4*)g_k) + b * 32 + lane);
    const float4* mp = ((const float4*)mem) + (size_t)r0 * 32 + lane;
    float4 m0 = __ldcs(mp);                  // streaming: no reuse this pass
    float4 m1 = __ldcs(mp + 32);
    float4 m2 = __ldcs(mp + 64);
    float4 m3 = __ldcs(mp + 96);

    float d0 = m0.x * k4.x + m0.y * k4.y + m0.z * k4.z + m0.w * k4.w;
    float n0 = m0.x * m0.x + m0.y * m0.y + m0.z * m0.z + m0.w * m0.w;
    float d1 = m1.x * k4.x + m1.y * k4.y + m1.z * k4.z + m1.w * k4.w;
    float n1 = m1.x * m1.x + m1.y * m1.y + m1.z * m1.z + m1.w * m1.w;
    float d2 = m2.x * k4.x + m2.y * k4.y + m2.z * k4.z + m2.w * k4.w;
    float n2 = m2.x * m2.x + m2.y * m2.y + m2.z * m2.z + m2.w * m2.w;
    float d3 = m3.x * k4.x + m3.y * k4.y + m3.z * k4.z + m3.w * k4.w;
    float n3 = m3.x * m3.x + m3.y * m3.y + m3.z * m3.z + m3.w * m3.w;
    #pragma unroll
    for (int o = 16; o; o >>= 1) {
        d0 += __shfl_xor_sync(0xffffffffu, d0, o);
        n0 += __shfl_xor_sync(0xffffffffu, n0, o);
        d1 += __shfl_xor_sync(0xffffffffu, d1, o);
        n1 += __shfl_xor_sync(0xffffffffu, n1, o);
        d2 += __shfl_xor_sync(0xffffffffu, d2, o);
        n2 += __shfl_xor_sync(0xffffffffu, n2, o);
        d3 += __shfl_xor_sync(0xffffffffu, d3, o);
        n3 += __shfl_xor_sync(0xffffffffu, n3, o);
    }
    if (lane == 0) {
        float normk = g_prm[b * 8 + 0];
        float beta  = g_prm[b * 8 + 1];
        g_s[r0]     = beta * (d0 / (normk * sqrtf(n0) + EPSF));
        g_s[r0 + 1] = beta * (d1 / (normk * sqrtf(n1) + EPSF));
        g_s[r0 + 2] = beta * (d2 / (normk * sqrtf(n2) + EPSF));
        g_s[r0 + 3] = beta * (d3 / (normk * sqrtf(n3) + EPSF));
    }
}

// ---------------- kernel 3: softmax + gate + shift + sharpen ----------------
// one block per batch, 1024 threads, 16 elems/thread (4 float4); w in 64KB smem
__global__ void __launch_bounds__(1024) weights_kernel(
    const float* __restrict__ prev, float* __restrict__ out)
{
    extern __shared__ float sw[];           // Nn floats = 64KB
    const int b = blockIdx.x, tid = threadIdx.x;
    const float gate  = g_prm[b * 8 + 2];
    const float gamma = g_prm[b * 8 + 3];
    const float s0 = g_prm[b * 8 + 4];
    const float s1 = g_prm[b * 8 + 5];
    const float s2 = g_prm[b * 8 + 6];

    const float4* s4 = (const float4*)(g_s + (size_t)b * Nn);
    const float4* p4 = (const float4*)(prev + (size_t)b * Nn);
    float4* sw4 = (float4*)sw;
    float4* o4 = (float4*)(out + (size_t)b * Nn);

    float4 sv[4];
    float mx = -3.4e38f;
    #pragma unroll
    for (int i = 0; i < 4; i++) {
        sv[i] = __ldcs(s4 + i * 1024 + tid);   // read-once: keep L2 clean
        mx = fmaxf(mx, fmaxf(fmaxf(sv[i].x, sv[i].y), fmaxf(sv[i].z, sv[i].w)));
    }
    mx = blockReduceMax1024(mx);

    float lsum = 0.0f;
    #pragma unroll
    for (int i = 0; i < 4; i++) {
        sv[i].x = __expf(sv[i].x - mx);
        sv[i].y = __expf(sv[i].y - mx);
        sv[i].z = __expf(sv[i].z - mx);
        sv[i].w = __expf(sv[i].w - mx);
        lsum += sv[i].x + sv[i].y + sv[i].z + sv[i].w;
    }
    float Z = blockReduceSum1024(lsum);

    const float gz = gate / Z;
    const float og = 1.0f - gate;
    #pragma unroll
    for (int i = 0; i < 4; i++) {
        float4 pv = __ldcs(p4 + i * 1024 + tid);   // read-once
        float4 wv;
        wv.x = sv[i].x * gz + og * pv.x;
        wv.y = sv[i].y * gz + og * pv.y;
        wv.z = sv[i].z * gz + og * pv.z;
        wv.w = sv[i].w * gz + og * pv.w;
        sw4[i * 1024 + tid] = wv;
        sv[i] = wv;                         // keep center taps in regs
    }
    __syncthreads();

    float4 wp[4];
    float psum = 0.0f;
    #pragma unroll
    for (int i = 0; i < 4; i++) {
        int n = (i * 1024 + tid) * 4;       // base index of this float4
        float wl = sw[(n - 1) & (Nn - 1)];
        float wr = sw[(n + 4) & (Nn - 1)];
        float4 wc = sv[i];
        float4 w2;
        w2.x = s0 * wl   + s1 * wc.x + s2 * wc.y;
        w2.y = s0 * wc.x + s1 * wc.y + s2 * wc.z;
        w2.z = s0 * wc.y + s1 * wc.z + s2 * wc.w;
        w2.w = s0 * wc.z + s1 * wc.w + s2 * wr;
        wp[i].x = exp2f(gamma * __log2f(w2.x));   // w2 strictly positive
        wp[i].y = exp2f(gamma * __log2f(w2.y));
        wp[i].z = exp2f(gamma * __log2f(w2.z));
        wp[i].w = exp2f(gamma * __log2f(w2.w));
        psum += wp[i].x + wp[i].y + wp[i].z + wp[i].w;
    }
    float S = blockReduceSum1024(psum);
    float inv = 1.0f / (S + EPSF);
    #pragma unroll
    for (int i = 0; i < 4; i++) {
        float4 ov;
        ov.x = wp[i].x * inv;
        ov.y = wp[i].y * inv;
        ov.z = wp[i].z * inv;
        ov.w = wp[i].w * inv;
        o4[i * 1024 + tid] = ov;            // default store: read pass reuses via L2
    }
}

// ---------------- kernel 4: weighted read partials (memory pass 2) ----------------
// 1024 blocks (64 batches x 16 chunks of 1024 rows); warp-per-row, 8 warps.
// Keep regs <= 32 (occupancy 8 blocks/SM); no fence/atomic here.
__global__ void __launch_bounds__(256, 8) read_kernel(
    const float* __restrict__ mem, const float* __restrict__ wts)
{
    const int b = blockIdx.x >> 4;           // /RCHUNKS
    const int c = blockIdx.x & (RCHUNKS - 1);
    const int wid = threadIdx.x >> 5, lane = threadIdx.x & 31;
    const int n0 = c * RROWS;

    float4 acc = make_float4(0.f, 0.f, 0.f, 0.f);
    for (int r = n0 + wid; r < n0 + RROWS; r += 8) {
        size_t row = (size_t)b * Nn + r;
        float wv = __ldg(wts + row);
        float4 m4 = __ldcs(((const float4*)mem) + row * 32 + lane);
        acc.x = fmaf(wv, m4.x, acc.x);
        acc.y = fmaf(wv, m4.y, acc.y);
        acc.z = fmaf(wv, m4.z, acc.z);
        acc.w = fmaf(wv, m4.w, acc.w);
    }

    __shared__ float sm[8][Mm];
    sm[wid][lane * 4 + 0] = acc.x;
    sm[wid][lane * 4 + 1] = acc.y;
    sm[wid][lane * 4 + 2] = acc.z;
    sm[wid][lane * 4 + 3] = acc.w;
    __syncthreads();
    if (threadIdx.x < Mm) {
        float s = 0.0f;
        #pragma unroll
        for (int j = 0; j < 8; j++) s += sm[j][threadIdx.x];
        g_part[(size_t)blockIdx.x * Mm + threadIdx.x] = s;
    }
}

// ---------------- kernel 5: fold partials ----------------
__global__ void __launch_bounds__(256) reduce_kernel(float* __restrict__ out)
{
    int idx = blockIdx.x * blockDim.x + threadIdx.x;
    if (idx >= Bsz * Mm) return;
    int b = idx >> 7, m = idx & 127;
    float s = 0.0f;
    #pragma unroll
    for (int j = 0; j < RCHUNKS; j++) s += g_part[((size_t)b * RCHUNKS + j) * Mm + m];
    out[(size_t)Bsz * Nn + idx] = s;
}

// ---------------- launch: single stream, full grids ----------------
extern "C" void kernel_launch(void* const* d_in, const int* in_sizes, int n_in,
                              void* d_out, int out_size)
{
    const float* ctrl    = (const float*)d_in[0];
    const float* prev    = (const float*)d_in[1];
    const float* mem     = (const float*)d_in[2];
    const float* key_w   = (const float*)d_in[3];
    const float* key_b   = (const float*)d_in[4];
    const float* beta_w  = (const float*)d_in[5];
    const float* beta_b  = (const float*)d_in[6];
    const float* gate_w  = (const float*)d_in[7];
    const float* gate_b  = (const float*)d_in[8];
    const float* shift_w = (const float*)d_in[9];
    const float* shift_b = (const float*)d_in[10];
    const float* gamma_w = (const float*)d_in[11];
    const float* gamma_b = (const float*)d_in[12];
    // d_in[13..16] = erase/add params: unused in read mode

    float* out = (float*)d_out;

    static bool attr_set = false;
    if (!attr_set) {
        cudaFuncSetAttribute(weights_kernel,
                             cudaFuncAttributeMaxDynamicSharedMemorySize,
                             Nn * (int)sizeof(float));
        attr_set = true;
    }

    proj_kernel<<<Bsz, 1024>>>(ctrl, key_w, key_b, beta_w, beta_b,
                               gate_w, gate_b, shift_w, shift_b, gamma_w, gamma_b);
    sim_kernel<<<(Bsz * Nn) / 32, 256>>>(mem);
    weights_kernel<<<Bsz, 1024, Nn * sizeof(float)>>>(prev, out);
    read_kernel<<<Bsz * RCHUNKS, 256>>>(mem, out);
    reduce_kernel<<<(Bsz * Mm + 255) / 256, 256>>>(out);
}